// round 14
// baseline (speedup 1.0000x reference)
#include <cuda_runtime.h>
#include <cstdint>

// NSbuilder — FINAL kernel (converged; confirmed over R10/R11/R13).
//
// L = 256 bitstream length, H = W = 512
// d_in[0] = src_ns [HW] f32, d_in[1] = src_st [HW] f32,
// d_in[2] = new_ns_len [HW] f32 (integer-valued in [0,256]), d_in[3] = rng [256] f32
//   (rng unused: it is the van der Corput sequence, rng[k] = bitrev8(k)/256,
//    folded into exact integer compares — see identity below)
// out: [256, 512, 512] f32
//
// Roofline, established over R2-R13: replay time is drain-bound at
// max(LTS ~43us, 268MB / ~5.7TB/s HBM write drain ~47us). Falsified levers:
// occupancy scaling (R4, flat), evict_first (R3, -35%), zero-read hot loop
// (R5, neutral), TMA bulk stores with zero STG (R7, neutral), evict_last L2
// residency (R9, neutral - dirty lines drain eagerly), 256-bit stores
// (R12, -15%). Output bytes are fixed by the problem; the floor is physical.
//
// Exact identity: thr > rng[k]  <=>  __brev(k) < (ceil(256*thr) << 24)
//   (256*thr is exact in fp32; for integer rev, rev < ceil(x) <=> rev < x)

#define L_BITS 256
#define HW     (512 * 512)
#define PIX4   (HW / 4)      // 65536 float4 pixel groups
#define TCHUNK 64            // t-planes per block (L_BITS / gridDim.y)

__device__ __forceinline__ unsigned thr24(float thr)
{
    int a = (int)ceilf(256.0f * thr);
    if (a <= 0)   return 0u;            // no bit ever set
    if (a >= 256) return 0xFFFFFFFFu;   // every bit set (rev<<24 <= 0xFF000000)
    return (unsigned)a << 24;
}

__global__ __launch_bounds__(256, 8)
void nsbuilder_kernel(const float* __restrict__ src_ns,
                      const float* __restrict__ src_st,
                      const float* __restrict__ nnl,
                      float* __restrict__ out)
{
    const int tid = threadIdx.x;
    const int g = blockIdx.x * blockDim.x + tid;    // float4 group id, < PIX4

    const float4 ns4 = reinterpret_cast<const float4*>(src_ns)[g];
    const float4 st4 = reinterpret_cast<const float4*>(src_st)[g];
    const float4 nl4 = reinterpret_cast<const float4*>(nnl)[g];

    const int nl[4] = {(int)nl4.x, (int)nl4.y, (int)nl4.z, (int)nl4.w};
    const unsigned A24[4] = {thr24(ns4.x), thr24(ns4.y), thr24(ns4.z), thr24(ns4.w)};
    const unsigned B24[4] = {thr24(st4.x), thr24(st4.y), thr24(st4.z), thr24(st4.w)};

    const int t0 = blockIdx.y * TCHUNK;
    float4* o = reinterpret_cast<float4*>(out) + (size_t)t0 * PIX4 + g;

    #pragma unroll 8
    for (int tt = 0; tt < TCHUNK; ++tt) {
        const int t = t0 + tt;
        float v[4];
        #pragma unroll
        for (int j = 0; j < 4; ++j) {
            const bool is_ns  = (t < nl[j]);
            const int  idx    = is_ns ? t : (t - nl[j]);      // always in [0,256)
            const unsigned th = is_ns ? A24[j] : B24[j];
            v[j] = (__brev((unsigned)idx) < th) ? 1.0f : 0.0f;
        }
        *o = make_float4(v[0], v[1], v[2], v[3]);   // coalesced STG.128
        o += PIX4;
    }
}

extern "C" void kernel_launch(void* const* d_in, const int* in_sizes, int n_in,
                              void* d_out, int out_size)
{
    const float* src_ns = (const float*)d_in[0];
    const float* src_st = (const float*)d_in[1];
    const float* nnl    = (const float*)d_in[2];
    float* out = (float*)d_out;

    dim3 grid(PIX4 / 256, L_BITS / TCHUNK);  // (256, 4) = 1024 blocks, one wave
    nsbuilder_kernel<<<grid, 256>>>(src_ns, src_st, nnl, out);
}

// round 15
// speedup vs baseline: 1.0007x; 1.0007x over previous
#include <cuda_runtime.h>
#include <cstdint>

// NSbuilder — FINAL kernel (converged; confirmed over R10/R11/R13/R14).
//
// L = 256 bitstream length, H = W = 512
// d_in[0] = src_ns [HW] f32, d_in[1] = src_st [HW] f32,
// d_in[2] = new_ns_len [HW] f32 (integer-valued in [0,256]), d_in[3] = rng [256] f32
//   (rng unused: it is the van der Corput sequence, rng[k] = bitrev8(k)/256,
//    folded into exact integer compares — see identity below)
// out: [256, 512, 512] f32
//
// Roofline, established over R2-R14: steady-state replay is pinned at
// 47.1-48.3us = 268MB of output at ~5.7TB/s sustained HBM write drain
// (back-to-back replays already overlap kernel with the prior drain tail, so
// this is the fully pipelined write-bandwidth limit). Falsified levers:
// occupancy scaling (R4, flat), evict_first (R3, -35%), zero-read hot loop
// (R5, neutral), TMA bulk stores with zero STG (R7, neutral), evict_last L2
// residency (R9, neutral - dirty lines write back eagerly), 256-bit stores
// (R12, -15%). Output bytes are fixed by the problem; the floor is physical.
//
// Exact identity: thr > rng[k]  <=>  __brev(k) < (ceil(256*thr) << 24)
//   (256*thr is exact in fp32; for integer rev, rev < ceil(x) <=> rev < x)

#define L_BITS 256
#define HW     (512 * 512)
#define PIX4   (HW / 4)      // 65536 float4 pixel groups
#define TCHUNK 64            // t-planes per block (L_BITS / gridDim.y)

__device__ __forceinline__ unsigned thr24(float thr)
{
    int a = (int)ceilf(256.0f * thr);
    if (a <= 0)   return 0u;            // no bit ever set
    if (a >= 256) return 0xFFFFFFFFu;   // every bit set (rev<<24 <= 0xFF000000)
    return (unsigned)a << 24;
}

__global__ __launch_bounds__(256, 8)
void nsbuilder_kernel(const float* __restrict__ src_ns,
                      const float* __restrict__ src_st,
                      const float* __restrict__ nnl,
                      float* __restrict__ out)
{
    const int tid = threadIdx.x;
    const int g = blockIdx.x * blockDim.x + tid;    // float4 group id, < PIX4

    const float4 ns4 = reinterpret_cast<const float4*>(src_ns)[g];
    const float4 st4 = reinterpret_cast<const float4*>(src_st)[g];
    const float4 nl4 = reinterpret_cast<const float4*>(nnl)[g];

    const int nl[4] = {(int)nl4.x, (int)nl4.y, (int)nl4.z, (int)nl4.w};
    const unsigned A24[4] = {thr24(ns4.x), thr24(ns4.y), thr24(ns4.z), thr24(ns4.w)};
    const unsigned B24[4] = {thr24(st4.x), thr24(st4.y), thr24(st4.z), thr24(st4.w)};

    const int t0 = blockIdx.y * TCHUNK;
    float4* o = reinterpret_cast<float4*>(out) + (size_t)t0 * PIX4 + g;

    #pragma unroll 8
    for (int tt = 0; tt < TCHUNK; ++tt) {
        const int t = t0 + tt;
        float v[4];
        #pragma unroll
        for (int j = 0; j < 4; ++j) {
            const bool is_ns  = (t < nl[j]);
            const int  idx    = is_ns ? t : (t - nl[j]);      // always in [0,256)
            const unsigned th = is_ns ? A24[j] : B24[j];
            v[j] = (__brev((unsigned)idx) < th) ? 1.0f : 0.0f;
        }
        *o = make_float4(v[0], v[1], v[2], v[3]);   // coalesced STG.128
        o += PIX4;
    }
}

extern "C" void kernel_launch(void* const* d_in, const int* in_sizes, int n_in,
                              void* d_out, int out_size)
{
    const float* src_ns = (const float*)d_in[0];
    const float* src_st = (const float*)d_in[1];
    const float* nnl    = (const float*)d_in[2];
    float* out = (float*)d_out;

    dim3 grid(PIX4 / 256, L_BITS / TCHUNK);  // (256, 4) = 1024 blocks, one wave
    nsbuilder_kernel<<<grid, 256>>>(src_ns, src_st, nnl, out);
}